// round 1
// baseline (speedup 1.0000x reference)
#include <cuda_runtime.h>
#include <cuda_bf16.h>

// SparseLinear: out[b, c] = sum_l w[b,l] * table[x[b,l], c]
// B=4096, L=200, C=128, table = 1,000,000 x 128 fp32.
// Inputs (metadata order): d_in[0]=x int32[4096*200], d_in[1]=w fp32[4096*200],
//                          d_in[2]=table fp32[1e6*128]. Output fp32[4096*128].

#define SL_B 4096
#define SL_L 200
#define SL_C 128

__global__ __launch_bounds__(SL_C) void sparse_linear_kernel(
    const int* __restrict__ x,
    const float* __restrict__ w,
    const float* __restrict__ table,
    float* __restrict__ out)
{
    __shared__ int   sx[SL_L];
    __shared__ float sw[SL_L];

    const int b = blockIdx.x;
    const int t = threadIdx.x;  // class column 0..127

    // Stage indices + weights for this batch row into shared memory.
    #pragma unroll
    for (int i = t; i < SL_L; i += SL_C) {
        sx[i] = x[b * SL_L + i];
        sw[i] = w[b * SL_L + i];
    }
    __syncthreads();

    float acc = 0.0f;

    // Unroll x8 -> 8 independent gathers in flight per thread (MLP ~ 8).
    #pragma unroll 8
    for (int l = 0; l < SL_L; ++l) {
        const unsigned off = (unsigned)sx[l] * (unsigned)SL_C + (unsigned)t;
        acc += sw[l] * __ldg(table + off);
    }

    out[b * SL_C + t] = acc;
}

extern "C" void kernel_launch(void* const* d_in, const int* in_sizes, int n_in,
                              void* d_out, int out_size)
{
    const int*   x     = (const int*)d_in[0];
    const float* w     = (const float*)d_in[1];
    const float* table = (const float*)d_in[2];
    float*       out   = (float*)d_out;

    sparse_linear_kernel<<<SL_B, SL_C>>>(x, w, table, out);
}

// round 2
// speedup vs baseline: 1.0313x; 1.0313x over previous
#include <cuda_runtime.h>
#include <cuda_bf16.h>

// SparseLinear: out[b, c] = sum_l w[b,l] * table[x[b,l], c]
// B=4096, L=200, C=128, table = 1,000,000 x 128 fp32 (512 MB).
//
// Strategy: per-CTA counting-sort of the 200 indices by top bits (64 buckets),
// so all concurrently-resident CTAs gather in ascending table-address order.
// The whole wave sweeps the table in a narrow moving window -> cross-CTA
// repeats hit L2, and the DRAM access stream gains row-buffer locality.

#define SL_B 4096
#define SL_L 200
#define SL_C 128
#define NBKT 64
#define BKT_SHIFT 14   // 1e6 rows < 2^20; top 6 bits -> 64 buckets of 16384 rows (8 MB)

__global__ __launch_bounds__(SL_C) void sparse_linear_kernel(
    const int* __restrict__ x,
    const float* __restrict__ w,
    const float* __restrict__ table,
    float* __restrict__ out)
{
    __shared__ int   sx[SL_L];
    __shared__ float sw[SL_L];
    __shared__ int   sx2[SL_L];   // address-sorted
    __shared__ float sw2[SL_L];
    __shared__ int   off[NBKT];   // bucket write cursors (exclusive prefix)

    const int b = blockIdx.x;
    const int t = threadIdx.x;    // class column 0..127

    if (t < NBKT) off[t] = 0;

    // Stage (x, w) for this batch row.
    #pragma unroll
    for (int i = t; i < SL_L; i += SL_C) {
        sx[i] = x[b * SL_L + i];
        sw[i] = w[b * SL_L + i];
    }
    __syncthreads();

    // Histogram by top bits.
    #pragma unroll
    for (int i = t; i < SL_L; i += SL_C) {
        atomicAdd(&off[sx[i] >> BKT_SHIFT], 1);
    }
    __syncthreads();

    // Exclusive prefix scan over 64 counts (warp 0, two 32-chunks via shfl).
    if (t < 32) {
        const unsigned FULL = 0xffffffffu;
        int c0 = off[t];
        int c1 = off[t + 32];
        int s0 = c0, s1 = c1;
        #pragma unroll
        for (int d = 1; d < 32; d <<= 1) {
            int n0 = __shfl_up_sync(FULL, s0, d);
            int n1 = __shfl_up_sync(FULL, s1, d);
            if (t >= d) { s0 += n0; s1 += n1; }
        }
        int tot0 = __shfl_sync(FULL, s0, 31);
        off[t]      = s0 - c0;          // exclusive
        off[t + 32] = tot0 + s1 - c1;
    }
    __syncthreads();

    // Scatter into bucket-sorted order (order within a bucket is arbitrary).
    #pragma unroll
    for (int i = t; i < SL_L; i += SL_C) {
        int   idx = sx[i];
        float wv  = sw[i];
        int p = atomicAdd(&off[idx >> BKT_SHIFT], 1);
        sx2[p] = idx;
        sw2[p] = wv;
    }
    __syncthreads();

    // Gather + accumulate in ascending-address order. Unroll x8 -> MLP ~8.
    float acc = 0.0f;
    #pragma unroll 8
    for (int l = 0; l < SL_L; ++l) {
        const unsigned o = (unsigned)sx2[l] * (unsigned)SL_C + (unsigned)t;
        acc += sw2[l] * __ldg(table + o);
    }

    out[b * SL_C + t] = acc;
}

extern "C" void kernel_launch(void* const* d_in, const int* in_sizes, int n_in,
                              void* d_out, int out_size)
{
    const int*   x     = (const int*)d_in[0];
    const float* w     = (const float*)d_in[1];
    const float* table = (const float*)d_in[2];
    float*       out   = (float*)d_out;

    sparse_linear_kernel<<<SL_B, SL_C>>>(x, w, table, out);
}